// round 3
// baseline (speedup 1.0000x reference)
#include <cuda_runtime.h>

// FocalBCELoss: loss = mean( -( t*log(p)*(1-p)^2*alpha[c] + (1-t)*log(1-p)*p^2 ) )
// N=262144, C=64, GAMMA=2. t is exactly 0.0 or 1.0 -> single-log branchless form:
//   bt = (t != 0); arg = bt?p:(1-p); u = bt?(1-p):p; s = bt?alpha:1
//   elem = -log(arg) * u*u * s
// Static partition: 1024 blocks x 256 thr, 16 float4/thread, unroll 4 (8 LDG.128 batched).

#define N_COLS   64
#define TOTAL    (262144 * 64)              // 16,777,216
#define TOTAL4   (TOTAL / 4)                // 4,194,304 float4s
#define NBLOCKS  1024
#define NTHREADS 256
#define NTHREADS_TOT (NBLOCKS * NTHREADS)   // 262,144
#define ITERS    (TOTAL4 / NTHREADS_TOT)    // 16
#define UNROLL   4

__device__ float g_partials[NBLOCKS];
__device__ unsigned int g_ticket;

__device__ __forceinline__ float focal_elem(float p, float t, float a)
{
    float q = 1.0f - p;
    bool  bt = (t != 0.0f);
    float arg = bt ? p : q;     // the prob whose log we take
    float u   = bt ? q : p;     // the modulating factor base
    float s   = bt ? a : 1.0f;  // per-class alpha only on positive branch
    return __logf(arg) * u * u * s;
}

__global__ __launch_bounds__(NTHREADS) void focal_fused_kernel(
    const float* __restrict__ inputs,
    const float* __restrict__ targets,
    const float* __restrict__ alpha,
    float* __restrict__ out)
{
    __shared__ float s_alpha[N_COLS];
    __shared__ float s_warp[NTHREADS / 32];
    __shared__ bool  s_is_last;

    int tid = threadIdx.x;
    if (tid < N_COLS) s_alpha[tid] = alpha[tid];
    __syncthreads();

    const float4* in4 = (const float4*)inputs;
    const float4* tg4 = (const float4*)targets;

    // column phase of this thread's float4 is invariant across iterations:
    // stride between iterations is NTHREADS_TOT float4s = 1,048,576 floats == 0 mod 64
    int c0 = (4 * (blockIdx.x * NTHREADS + tid)) & (N_COLS - 1);
    float a0 = s_alpha[c0 + 0];
    float a1 = s_alpha[c0 + 1];
    float a2 = s_alpha[c0 + 2];
    float a3 = s_alpha[c0 + 3];

    int base = blockIdx.x * NTHREADS + tid;

    float acc0 = 0.0f, acc1 = 0.0f;

    #pragma unroll
    for (int k = 0; k < ITERS; k += UNROLL) {
        // batch all 8 loads first (max MLP)
        float4 p0 = __ldcs(&in4[base + (k + 0) * NTHREADS_TOT]);
        float4 p1 = __ldcs(&in4[base + (k + 1) * NTHREADS_TOT]);
        float4 p2 = __ldcs(&in4[base + (k + 2) * NTHREADS_TOT]);
        float4 p3 = __ldcs(&in4[base + (k + 3) * NTHREADS_TOT]);
        float4 t0 = __ldcs(&tg4[base + (k + 0) * NTHREADS_TOT]);
        float4 t1 = __ldcs(&tg4[base + (k + 1) * NTHREADS_TOT]);
        float4 t2 = __ldcs(&tg4[base + (k + 2) * NTHREADS_TOT]);
        float4 t3 = __ldcs(&tg4[base + (k + 3) * NTHREADS_TOT]);

        acc0 -= focal_elem(p0.x, t0.x, a0);
        acc1 -= focal_elem(p0.y, t0.y, a1);
        acc0 -= focal_elem(p0.z, t0.z, a2);
        acc1 -= focal_elem(p0.w, t0.w, a3);

        acc0 -= focal_elem(p1.x, t1.x, a0);
        acc1 -= focal_elem(p1.y, t1.y, a1);
        acc0 -= focal_elem(p1.z, t1.z, a2);
        acc1 -= focal_elem(p1.w, t1.w, a3);

        acc0 -= focal_elem(p2.x, t2.x, a0);
        acc1 -= focal_elem(p2.y, t2.y, a1);
        acc0 -= focal_elem(p2.z, t2.z, a2);
        acc1 -= focal_elem(p2.w, t2.w, a3);

        acc0 -= focal_elem(p3.x, t3.x, a0);
        acc1 -= focal_elem(p3.y, t3.y, a1);
        acc0 -= focal_elem(p3.z, t3.z, a2);
        acc1 -= focal_elem(p3.w, t3.w, a3);
    }

    float acc = acc0 + acc1;

    // block reduce
    #pragma unroll
    for (int off = 16; off > 0; off >>= 1)
        acc += __shfl_down_sync(0xFFFFFFFFu, acc, off);

    int lane = tid & 31;
    int wid  = tid >> 5;
    if (lane == 0) s_warp[wid] = acc;
    __syncthreads();

    if (wid == 0) {
        float v = (lane < NTHREADS / 32) ? s_warp[lane] : 0.0f;
        #pragma unroll
        for (int off = 16; off > 0; off >>= 1)
            v += __shfl_down_sync(0xFFFFFFFFu, v, off);
        if (lane == 0) {
            g_partials[blockIdx.x] = v;
            __threadfence();
            unsigned int t = atomicInc(&g_ticket, NBLOCKS - 1);
            s_is_last = (t == NBLOCKS - 1);
        }
    }
    __syncthreads();

    // last block: deterministic fixed-order final sum
    if (s_is_last) {
        float facc = 0.0f;
        for (int i = tid; i < NBLOCKS; i += NTHREADS)
            facc += g_partials[i];

        #pragma unroll
        for (int off = 16; off > 0; off >>= 1)
            facc += __shfl_down_sync(0xFFFFFFFFu, facc, off);

        if (lane == 0) s_warp[wid] = facc;
        __syncthreads();

        if (wid == 0) {
            float v = (lane < NTHREADS / 32) ? s_warp[lane] : 0.0f;
            #pragma unroll
            for (int off = 16; off > 0; off >>= 1)
                v += __shfl_down_sync(0xFFFFFFFFu, v, off);
            if (lane == 0)
                out[0] = v * (1.0f / (float)TOTAL);
        }
    }
}

extern "C" void kernel_launch(void* const* d_in, const int* in_sizes, int n_in,
                              void* d_out, int out_size)
{
    const float* inputs  = (const float*)d_in[0];
    const float* targets = (const float*)d_in[1];
    const float* alpha   = (const float*)d_in[2];
    float* out = (float*)d_out;

    focal_fused_kernel<<<NBLOCKS, NTHREADS>>>(inputs, targets, alpha, out);
}

// round 4
// speedup vs baseline: 1.0786x; 1.0786x over previous
#include <cuda_runtime.h>

// FocalBCELoss: loss = mean( -( t*log(p)*(1-p)^2*alpha[c] + (1-t)*log(1-p)*p^2 ) )
// N=262144, C=64, GAMMA=2. t in {0,1} -> single-log select form.
// 2048 blocks x 256 threads = 524288 threads, exactly 8 float4/thread,
// pair-unrolled (4 LDG.128 in flight), fused last-block-done reduction.

#define N_COLS   64
#define TOTAL    (262144 * 64)              // 16,777,216
#define TOTAL4   (TOTAL / 4)                // 4,194,304 float4s
#define NBLOCKS  2048
#define NTHREADS 256
#define NTH_TOT  (NBLOCKS * NTHREADS)       // 524,288
#define ITERS    (TOTAL4 / NTH_TOT)         // 8 exactly

__device__ float g_partials[NBLOCKS];
__device__ unsigned int g_ticket;

__device__ __forceinline__ float focal_elem(float p, float t, float a)
{
    float q = 1.0f - p;
    bool  bt = (t != 0.0f);
    float arg = bt ? p : q;
    float u   = bt ? q : p;
    float s   = bt ? a : 1.0f;
    return __logf(arg) * u * u * s;
}

__global__ __launch_bounds__(NTHREADS) void focal_fused_kernel(
    const float* __restrict__ inputs,
    const float* __restrict__ targets,
    const float* __restrict__ alpha,
    float* __restrict__ out)
{
    __shared__ float s_alpha[N_COLS];
    __shared__ float s_warp[NTHREADS / 32];
    __shared__ bool  s_is_last;

    int tid = threadIdx.x;
    if (tid < N_COLS) s_alpha[tid] = alpha[tid];
    __syncthreads();

    const float4* in4 = (const float4*)inputs;
    const float4* tg4 = (const float4*)targets;

    int gid = blockIdx.x * NTHREADS + tid;

    // stride between iterations (NTH_TOT float4s = 2,097,152 floats) is 0 mod 64,
    // so this thread's column phase is constant -> hoist alpha.
    int c0 = (4 * gid) & (N_COLS - 1);
    float a0 = s_alpha[c0 + 0];
    float a1 = s_alpha[c0 + 1];
    float a2 = s_alpha[c0 + 2];
    float a3 = s_alpha[c0 + 3];

    float acc0 = 0.0f, acc1 = 0.0f;

    #pragma unroll
    for (int k = 0; k < ITERS; k += 2) {
        int i0 = gid + (k + 0) * NTH_TOT;
        int i1 = gid + (k + 1) * NTH_TOT;

        // 4 LDG.128 batched (16 data regs in flight)
        float4 p0 = __ldcs(&in4[i0]);
        float4 p1 = __ldcs(&in4[i1]);
        float4 t0 = __ldcs(&tg4[i0]);
        float4 t1 = __ldcs(&tg4[i1]);

        acc0 -= focal_elem(p0.x, t0.x, a0);
        acc1 -= focal_elem(p0.y, t0.y, a1);
        acc0 -= focal_elem(p0.z, t0.z, a2);
        acc1 -= focal_elem(p0.w, t0.w, a3);

        acc0 -= focal_elem(p1.x, t1.x, a0);
        acc1 -= focal_elem(p1.y, t1.y, a1);
        acc0 -= focal_elem(p1.z, t1.z, a2);
        acc1 -= focal_elem(p1.w, t1.w, a3);
    }

    float acc = acc0 + acc1;

    // block reduce
    #pragma unroll
    for (int off = 16; off > 0; off >>= 1)
        acc += __shfl_down_sync(0xFFFFFFFFu, acc, off);

    int lane = tid & 31;
    int wid  = tid >> 5;
    if (lane == 0) s_warp[wid] = acc;
    __syncthreads();

    if (wid == 0) {
        float v = (lane < NTHREADS / 32) ? s_warp[lane] : 0.0f;
        #pragma unroll
        for (int off = 16; off > 0; off >>= 1)
            v += __shfl_down_sync(0xFFFFFFFFu, v, off);
        if (lane == 0) {
            g_partials[blockIdx.x] = v;
            __threadfence();
            unsigned int t = atomicInc(&g_ticket, NBLOCKS - 1);
            s_is_last = (t == NBLOCKS - 1);
        }
    }
    __syncthreads();

    // last block: deterministic fixed-order final sum
    if (s_is_last) {
        float facc = 0.0f;
        #pragma unroll
        for (int i = tid; i < NBLOCKS; i += NTHREADS)
            facc += g_partials[i];

        #pragma unroll
        for (int off = 16; off > 0; off >>= 1)
            facc += __shfl_down_sync(0xFFFFFFFFu, facc, off);

        if (lane == 0) s_warp[wid] = facc;
        __syncthreads();

        if (wid == 0) {
            float v = (lane < NTHREADS / 32) ? s_warp[lane] : 0.0f;
            #pragma unroll
            for (int off = 16; off > 0; off >>= 1)
                v += __shfl_down_sync(0xFFFFFFFFu, v, off);
            if (lane == 0)
                out[0] = v * (1.0f / (float)TOTAL);
        }
    }
}

extern "C" void kernel_launch(void* const* d_in, const int* in_sizes, int n_in,
                              void* d_out, int out_size)
{
    const float* inputs  = (const float*)d_in[0];
    const float* targets = (const float*)d_in[1];
    const float* alpha   = (const float*)d_in[2];
    float* out = (float*)d_out;

    focal_fused_kernel<<<NBLOCKS, NTHREADS>>>(inputs, targets, alpha, out);
}

// round 5
// speedup vs baseline: 1.1346x; 1.0519x over previous
#include <cuda_runtime.h>

// FocalBCELoss: loss = mean( -( t*log(p)*(1-p)^2*alpha[c] + (1-t)*log(1-p)*p^2 ) )
// N = 262144, C = 64, GAMMA = 2.
// R1's proven main loop (1184 blocks = 148 SMs x 8 = one perfect wave, grid-stride,
// plain float4 loads, 2-log math) + fused last-block-done final reduction.

#define N_ROWS   262144
#define N_COLS   64
#define TOTAL    (N_ROWS * N_COLS)          // 16,777,216 elements
#define TOTAL4   (TOTAL / 4)                // 4,194,304 float4s
#define NBLOCKS  1184                       // 148 SMs * 8 resident blocks -> 1 wave
#define NTHREADS 256

__device__ float g_partials[NBLOCKS];
__device__ unsigned int g_ticket;

__global__ __launch_bounds__(NTHREADS) void focal_fused_kernel(
    const float* __restrict__ inputs,
    const float* __restrict__ targets,
    const float* __restrict__ alpha,
    float* __restrict__ out)
{
    __shared__ float s_alpha[N_COLS];
    __shared__ float s_warp[NTHREADS / 32];
    __shared__ bool  s_is_last;

    int tid = threadIdx.x;
    if (tid < N_COLS) s_alpha[tid] = alpha[tid];
    __syncthreads();

    const float4* in4 = (const float4*)inputs;
    const float4* tg4 = (const float4*)targets;

    float acc = 0.0f;

    // grid-stride over float4 elements — identical to the R1 main loop
    for (int i = blockIdx.x * NTHREADS + tid; i < TOTAL4; i += NBLOCKS * NTHREADS) {
        float4 p = in4[i];
        float4 t = tg4[i];
        int c0 = (i * 4) & (N_COLS - 1);

        float a0 = s_alpha[c0 + 0];
        float a1 = s_alpha[c0 + 1];
        float a2 = s_alpha[c0 + 2];
        float a3 = s_alpha[c0 + 3];

        {
            float q = 1.0f - p.x;
            float left  = t.x * __logf(p.x) * q * q * a0;
            float right = (1.0f - t.x) * __logf(q) * p.x * p.x;
            acc -= left + right;
        }
        {
            float q = 1.0f - p.y;
            float left  = t.y * __logf(p.y) * q * q * a1;
            float right = (1.0f - t.y) * __logf(q) * p.y * p.y;
            acc -= left + right;
        }
        {
            float q = 1.0f - p.z;
            float left  = t.z * __logf(p.z) * q * q * a2;
            float right = (1.0f - t.z) * __logf(q) * p.z * p.z;
            acc -= left + right;
        }
        {
            float q = 1.0f - p.w;
            float left  = t.w * __logf(p.w) * q * q * a3;
            float right = (1.0f - t.w) * __logf(q) * p.w * p.w;
            acc -= left + right;
        }
    }

    // block reduce
    #pragma unroll
    for (int off = 16; off > 0; off >>= 1)
        acc += __shfl_down_sync(0xFFFFFFFFu, acc, off);

    int lane = tid & 31;
    int wid  = tid >> 5;
    if (lane == 0) s_warp[wid] = acc;
    __syncthreads();

    if (wid == 0) {
        float v = (lane < NTHREADS / 32) ? s_warp[lane] : 0.0f;
        #pragma unroll
        for (int off = 16; off > 0; off >>= 1)
            v += __shfl_down_sync(0xFFFFFFFFu, v, off);
        if (lane == 0) {
            g_partials[blockIdx.x] = v;
            __threadfence();
            unsigned int t = atomicInc(&g_ticket, NBLOCKS - 1);
            s_is_last = (t == NBLOCKS - 1);
        }
    }
    __syncthreads();

    // last-arriving block: deterministic fixed-order final sum
    if (s_is_last) {
        float facc = 0.0f;
        for (int i = tid; i < NBLOCKS; i += NTHREADS)
            facc += g_partials[i];

        #pragma unroll
        for (int off = 16; off > 0; off >>= 1)
            facc += __shfl_down_sync(0xFFFFFFFFu, facc, off);

        if (lane == 0) s_warp[wid] = facc;
        __syncthreads();

        if (wid == 0) {
            float v = (lane < NTHREADS / 32) ? s_warp[lane] : 0.0f;
            #pragma unroll
            for (int off = 16; off > 0; off >>= 1)
                v += __shfl_down_sync(0xFFFFFFFFu, v, off);
            if (lane == 0)
                out[0] = v * (1.0f / (float)TOTAL);
        }
    }
}

extern "C" void kernel_launch(void* const* d_in, const int* in_sizes, int n_in,
                              void* d_out, int out_size)
{
    const float* inputs  = (const float*)d_in[0];
    const float* targets = (const float*)d_in[1];
    const float* alpha   = (const float*)d_in[2];
    float* out = (float*)d_out;

    focal_fused_kernel<<<NBLOCKS, NTHREADS>>>(inputs, targets, alpha, out);
}